// round 1
// baseline (speedup 1.0000x reference)
#include <cuda_runtime.h>
#include <cstdint>

#define N_NODES 40000
#define N_EDGES 640000
#define D 128
#define BN_EPS 1e-5f

// ---------------- device scratch (no allocations allowed) ----------------
__device__ float g_agg[(size_t)N_NODES * D];   // segment sums
__device__ float g_deg[N_NODES];               // degrees
__device__ float g_invdeg[N_NODES];            // 1/max(deg,1)
__device__ float g_y[(size_t)N_NODES * D];     // pre-batchnorm activations
__device__ float g_colsum[D];
__device__ float g_colsq[D];
__device__ float g_scale[D];
__device__ float g_shift[D];

// ---------------- K1: zero scratch ----------------
__global__ void k_zero() {
    int i = blockIdx.x * blockDim.x + threadIdx.x;
    int total4 = N_NODES * D / 4;
    if (i < total4) {
        ((float4*)g_agg)[i] = make_float4(0.f, 0.f, 0.f, 0.f);
    }
    if (i < N_NODES) g_deg[i] = 0.f;
    if (i < D) { g_colsum[i] = 0.f; g_colsq[i] = 0.f; }
}

// ---------------- K2: edge scatter (warp per edge) ----------------
__global__ void __launch_bounds__(256) k_scatter(const float* __restrict__ h,
                                                 const int* __restrict__ src,
                                                 const int* __restrict__ dst) {
    int gtid = blockIdx.x * blockDim.x + threadIdx.x;
    int e = gtid >> 5;            // edge index
    int lane = gtid & 31;         // 32 lanes x float4 = 128 floats
    if (e >= N_EDGES) return;
    int s = src[e];
    int d = dst[e];
    float4 v = ((const float4*)(h))[(size_t)s * (D / 4) + lane];
    float* p = g_agg + (size_t)d * D + lane * 4;
    asm volatile("red.global.add.v4.f32 [%0], {%1,%2,%3,%4};"
                 :: "l"(p), "f"(v.x), "f"(v.y), "f"(v.z), "f"(v.w)
                 : "memory");
    if (lane == 0) atomicAdd(&g_deg[d], 1.0f);
}

// ---------------- K3: inverse degree ----------------
__global__ void k_invdeg() {
    int i = blockIdx.x * blockDim.x + threadIdx.x;
    if (i < N_NODES) g_invdeg[i] = 1.0f / fmaxf(g_deg[i], 1.0f);
}

// ---------------- K4: fused dual GEMM + bias + relu + snorm + col stats ----
// out_pre = relu(h@Ws + (agg*invdeg)@Wn + b) * snorm   -> g_y
// also accumulates per-column sum / sumsq into g_colsum/g_colsq.
// BM=64 rows per block, BN=128 (all cols), K=256 (h ++ hneigh), BK=16.
// 256 threads, each computes an 8x4 microtile.
#define BM 64
#define BK 16
__global__ void __launch_bounds__(256) k_gemm(const float* __restrict__ h,
                                              const float* __restrict__ Ws,
                                              const float* __restrict__ Wn,
                                              const float* __restrict__ bias,
                                              const float* __restrict__ snorm) {
    __shared__ float As[BK][BM];       // [k][row]
    __shared__ float Bs[BK][D];        // [k][col]
    __shared__ float red[8][D];        // epilogue reduction buffer

    const int tid = threadIdx.x;
    const int cx  = tid & 31;          // col group: cols cx*4 .. cx*4+3
    const int ry  = tid >> 5;          // row group: rows ry*8 .. ry*8+7
    const int row0 = blockIdx.x * BM;

    // A-tile loader mapping: each thread loads one float4 along k
    const int lrow = tid >> 2;         // 0..63
    const int kq   = tid & 3;          // 0..3  (k quad within BK)
    const int grow = row0 + lrow;
    const float invd = g_invdeg[grow];

    float acc[8][4];
    #pragma unroll
    for (int j = 0; j < 8; j++)
        #pragma unroll
        for (int c = 0; c < 4; c++) acc[j][c] = 0.f;

    for (int kc = 0; kc < 2 * D; kc += BK) {
        // ---- load A tile (transposed into [k][row]) ----
        int kg = kc + kq * 4;
        float4 a4;
        if (kg < D) {
            a4 = *(const float4*)(h + (size_t)grow * D + kg);
        } else {
            a4 = *(const float4*)(g_agg + (size_t)grow * D + (kg - D));
            a4.x *= invd; a4.y *= invd; a4.z *= invd; a4.w *= invd;
        }
        As[kq * 4 + 0][lrow] = a4.x;
        As[kq * 4 + 1][lrow] = a4.y;
        As[kq * 4 + 2][lrow] = a4.z;
        As[kq * 4 + 3][lrow] = a4.w;

        // ---- load B tile ----
        #pragma unroll
        for (int i = 0; i < 2; i++) {
            int li = tid + i * 256;
            int kk = li >> 5;
            int n4 = li & 31;
            int kgb = kc + kk;
            const float* Wp = (kgb < D) ? (Ws + (size_t)kgb * D)
                                        : (Wn + (size_t)(kgb - D) * D);
            *(float4*)&Bs[kk][n4 * 4] = *(const float4*)(Wp + n4 * 4);
        }
        __syncthreads();

        // ---- compute ----
        #pragma unroll
        for (int k = 0; k < BK; k++) {
            float4 b4 = *(float4*)&Bs[k][cx * 4];
            float4 a0 = *(float4*)&As[k][ry * 8];
            float4 a1 = *(float4*)&As[k][ry * 8 + 4];
            float a[8] = {a0.x, a0.y, a0.z, a0.w, a1.x, a1.y, a1.z, a1.w};
            #pragma unroll
            for (int j = 0; j < 8; j++) {
                acc[j][0] += a[j] * b4.x;
                acc[j][1] += a[j] * b4.y;
                acc[j][2] += a[j] * b4.z;
                acc[j][3] += a[j] * b4.w;
            }
        }
        __syncthreads();
    }

    // ---- epilogue: bias + relu + snorm, write y, accumulate col stats ----
    float4 bb = *(const float4*)(bias + cx * 4);
    float lsum[4] = {0.f, 0.f, 0.f, 0.f};
    float lsq[4]  = {0.f, 0.f, 0.f, 0.f};
    #pragma unroll
    for (int j = 0; j < 8; j++) {
        int r = row0 + ry * 8 + j;
        float sn = snorm[r];
        float4 v;
        v.x = fmaxf(acc[j][0] + bb.x, 0.f) * sn;
        v.y = fmaxf(acc[j][1] + bb.y, 0.f) * sn;
        v.z = fmaxf(acc[j][2] + bb.z, 0.f) * sn;
        v.w = fmaxf(acc[j][3] + bb.w, 0.f) * sn;
        *(float4*)(g_y + (size_t)r * D + cx * 4) = v;
        lsum[0] += v.x; lsum[1] += v.y; lsum[2] += v.z; lsum[3] += v.w;
        lsq[0] += v.x * v.x; lsq[1] += v.y * v.y;
        lsq[2] += v.z * v.z; lsq[3] += v.w * v.w;
    }

    *(float4*)&red[ry][cx * 4] = make_float4(lsum[0], lsum[1], lsum[2], lsum[3]);
    __syncthreads();
    if (tid < D) {
        float s = 0.f;
        #pragma unroll
        for (int r = 0; r < 8; r++) s += red[r][tid];
        atomicAdd(&g_colsum[tid], s);
    }
    __syncthreads();
    *(float4*)&red[ry][cx * 4] = make_float4(lsq[0], lsq[1], lsq[2], lsq[3]);
    __syncthreads();
    if (tid < D) {
        float s = 0.f;
        #pragma unroll
        for (int r = 0; r < 8; r++) s += red[r][tid];
        atomicAdd(&g_colsq[tid], s);
    }
}

// ---------------- K5: batchnorm finalize (fold into scale/shift) ----------
__global__ void k_bn(const float* __restrict__ gamma, const float* __restrict__ beta) {
    int c = threadIdx.x;
    if (c >= D) return;
    float m  = g_colsum[c] * (1.0f / N_NODES);
    float v  = g_colsq[c] * (1.0f / N_NODES) - m * m;
    float rs = rsqrtf(v + BN_EPS);
    float sc = rs * gamma[c];
    g_scale[c] = sc;
    g_shift[c] = beta[c] - m * sc;
}

// ---------------- K6: out = h + y*scale + shift ----------------
__global__ void __launch_bounds__(256) k_final(const float* __restrict__ h,
                                               float* __restrict__ out) {
    int i = blockIdx.x * blockDim.x + threadIdx.x;
    if (i >= N_NODES * (D / 4)) return;
    int c4 = i & (D / 4 - 1);
    float4 y  = ((const float4*)g_y)[i];
    float4 hh = ((const float4*)h)[i];
    float4 sc = *(const float4*)&g_scale[c4 * 4];
    float4 sh = *(const float4*)&g_shift[c4 * 4];
    float4 o;
    o.x = hh.x + y.x * sc.x + sh.x;
    o.y = hh.y + y.y * sc.y + sh.y;
    o.z = hh.z + y.z * sc.z + sh.z;
    o.w = hh.w + y.w * sc.w + sh.w;
    ((float4*)out)[i] = o;
}

// ---------------- launch ----------------
extern "C" void kernel_launch(void* const* d_in, const int* in_sizes, int n_in,
                              void* d_out, int out_size) {
    const float* h      = (const float*)d_in[0];
    const float* snorm  = (const float*)d_in[1];
    const float* Ws     = (const float*)d_in[2];
    const float* Wn     = (const float*)d_in[3];
    const float* bias   = (const float*)d_in[4];
    const float* gamma  = (const float*)d_in[5];
    const float* beta   = (const float*)d_in[6];
    const int*   src    = (const int*)d_in[7];
    const int*   dst    = (const int*)d_in[8];
    float* out = (float*)d_out;

    int zero_blocks = (N_NODES * D / 4 + 255) / 256;
    k_zero<<<zero_blocks, 256>>>();

    int scatter_blocks = (N_EDGES * 32) / 256;       // warp per edge
    k_scatter<<<scatter_blocks, 256>>>(h, src, dst);

    k_invdeg<<<(N_NODES + 255) / 256, 256>>>();

    k_gemm<<<N_NODES / BM, 256>>>(h, Ws, Wn, bias, snorm);

    k_bn<<<1, D>>>(gamma, beta);

    k_final<<<(N_NODES * (D / 4) + 255) / 256, 256>>>(h, out);
}